// round 1
// baseline (speedup 1.0000x reference)
#include <cuda_runtime.h>

// InstanceDiceLoss on GB300.
// Inputs (metadata order): d_in[0] = x (pred) [2,1,128,128,128] f32,
//                          d_in[1] = y (gt)   [2,1,128,128,128] f32.
// Output: scalar f32 instance dice.
//
// Pipeline (all graph-capturable, no allocations):
//  k_zero     : zero counters + overlap histogram
//  k_init     : threshold -> union-find parent init + active voxel list (sparse!)
//  k_merge    : lock-free union-find (atomicMin) over 13 forward 26-neighbors
//  k_flatten  : path-flatten roots, init per-root maxid slot
//  k_maxroot  : per-component max initial id (atomicMax) + gather roots
//  k_compact  : per volume: sort <=64 roots by maxid, assign compact ids 1..k
//  k_overlap  : 65x65 overlap histogram from active lists (batch-merged ids)
//  k_final    : dice formula -> scalar

#define VOXB 21
#define VOX (1 << VOXB)            // 128^3
#define NVOL 4                     // gt_s0, gt_s1, pr_s0, pr_s1
#define MAXLAB 64
#define MM 65                      // MAX_LAB + 1

__device__ int      d_W[NVOL * VOX];       // union-find parent / root (-1 = bg)
__device__ int      d_A[NVOL * VOX];       // per-root: maxid then compact id
__device__ int      d_active[NVOL * VOX];  // active voxel list (global ids)
__device__ int      d_activeCnt;
__device__ int      d_rootCnt[NVOL];
__device__ int      d_rootList[NVOL * MAXLAB];
__device__ unsigned d_ov[MM * MM];         // overlap histogram

__global__ void k_zero() {
    int i = blockIdx.x * blockDim.x + threadIdx.x;
    if (i == 0) d_activeCnt = 0;
    if (i < NVOL) d_rootCnt[i] = 0;
    if (i < MM * MM) d_ov[i] = 0u;
}

__global__ void __launch_bounds__(256) k_init(const float* __restrict__ x,
                                              const float* __restrict__ y) {
    int i = blockIdx.x * blockDim.x + threadIdx.x;
    __shared__ int s_cnt, s_base;
    if (threadIdx.x == 0) s_cnt = 0;
    __syncthreads();
    bool mask = false;
    int slot = 0;
    if (i < NVOL * VOX) {
        int vol = i >> VOXB;
        int local = i & (VOX - 1);
        float v = (vol < 2) ? y[(vol << VOXB) + local]
                            : x[((vol - 2) << VOXB) + local];
        mask = v > 0.5f;
        d_W[i] = mask ? local : -1;
        if (mask) slot = atomicAdd(&s_cnt, 1);
    }
    __syncthreads();
    if (threadIdx.x == 0)
        s_base = (s_cnt > 0) ? atomicAdd(&d_activeCnt, s_cnt) : 0;
    __syncthreads();
    if (mask) d_active[s_base + slot] = i;
}

// Classic lock-free union (Komura): repeatedly attach larger label under smaller.
__device__ __forceinline__ void unite(int* W, int a, int b) {
    while (a != b) {
        if (a < b) { int t = a; a = b; b = t; }  // a > b
        int old = atomicMin(&W[a], b);
        if (old == a) return;  // a was a root; now linked to b
        a = old;               // keep merging old parent with b
    }
}

__global__ void __launch_bounds__(256) k_merge() {
    int n = d_activeCnt;
    for (int t = blockIdx.x * blockDim.x + threadIdx.x; t < n;
         t += gridDim.x * blockDim.x) {
        int gid = d_active[t];
        int vol = gid >> VOXB;
        int local = gid & (VOX - 1);
        int* W = d_W + (vol << VOXB);
        int z = local >> 14, yy = (local >> 7) & 127, xx = local & 127;
#pragma unroll
        for (int dz = 0; dz <= 1; dz++)
#pragma unroll
            for (int dy = -1; dy <= 1; dy++)
#pragma unroll
                for (int dx = -1; dx <= 1; dx++) {
                    // forward half of 26-neighborhood (13 offsets)
                    if (dz == 0 && (dy < 0 || (dy == 0 && dx <= 0))) continue;
                    int nz = z + dz, ny = yy + dy, nx = xx + dx;
                    if ((unsigned)nz >= 128u || (unsigned)ny >= 128u ||
                        (unsigned)nx >= 128u)
                        continue;
                    int nl = (nz << 14) | (ny << 7) | nx;
                    if (__ldcg(&W[nl]) >= 0) unite(W, local, nl);
                }
    }
}

__global__ void __launch_bounds__(256) k_flatten() {
    int n = d_activeCnt;
    for (int t = blockIdx.x * blockDim.x + threadIdx.x; t < n;
         t += gridDim.x * blockDim.x) {
        int gid = d_active[t];
        int vol = gid >> VOXB;
        int local = gid & (VOX - 1);
        const int* W = d_W + (vol << VOXB);
        int r = local;
        int p = W[r];
        while (p != r) { r = p; p = W[r]; }
        d_W[gid] = r;
        if (r == local) d_A[gid] = 0;  // init maxid slot at root
    }
}

__global__ void __launch_bounds__(256) k_maxroot() {
    int n = d_activeCnt;
    for (int t = blockIdx.x * blockDim.x + threadIdx.x; t < n;
         t += gridDim.x * blockDim.x) {
        int gid = d_active[t];
        int vol = gid >> VOXB;
        int local = gid & (VOX - 1);
        int r = d_W[gid];
        atomicMax(&d_A[(vol << VOXB) + r], local + 1);
        if (r == local) {
            int slot = atomicAdd(&d_rootCnt[vol], 1);
            if (slot < MAXLAB) d_rootList[vol * MAXLAB + slot] = local;
        }
    }
}

// One thread per volume: sort roots by component maxid (matches jnp.unique
// ordering on CC labels), write compact ids 1..k into d_A[root].
__global__ void k_compact() {
    int vol = threadIdx.x;
    if (vol >= NVOL) return;
    int k = d_rootCnt[vol];
    if (k > MAXLAB) k = MAXLAB;
    int roots[MAXLAB];
    int mx[MAXLAB];
    for (int i = 0; i < k; i++) {
        roots[i] = d_rootList[vol * MAXLAB + i];
        mx[i] = d_A[(vol << VOXB) + roots[i]];
    }
    for (int i = 1; i < k; i++) {  // insertion sort by maxid asc
        int r = roots[i], m = mx[i], j = i - 1;
        while (j >= 0 && mx[j] > m) {
            mx[j + 1] = mx[j]; roots[j + 1] = roots[j]; j--;
        }
        mx[j + 1] = m; roots[j + 1] = r;
    }
    for (int i = 0; i < k; i++) d_A[(vol << VOXB) + roots[i]] = i + 1;
}

__global__ void __launch_bounds__(256) k_overlap() {
    int n = d_activeCnt;
    for (int t = blockIdx.x * blockDim.x + threadIdx.x; t < n;
         t += gridDim.x * blockDim.x) {
        int gid = d_active[t];
        int vol = gid >> VOXB;
        int local = gid & (VOX - 1);
        if (vol < 2) {  // gt voxel: record (g, p) for any p
            int g = d_A[(vol << VOXB) + d_W[gid]];
            int pv = vol + 2;
            int wp = d_W[(pv << VOXB) + local];
            int p = (wp >= 0) ? d_A[(pv << VOXB) + wp] : 0;
            atomicAdd(&d_ov[g * MM + p], 1u);
        } else {  // pr voxel: record (0, p) only where gt is background
            int gv = vol - 2;
            int wg = d_W[(gv << VOXB) + local];
            if (wg < 0) {
                int p = d_A[(vol << VOXB) + d_W[gid]];
                atomicAdd(&d_ov[p], 1u);
            }
        }
    }
}

__global__ void k_final(float* __restrict__ out) {
    __shared__ float prs[MM];
    __shared__ float dice_s[MM];
    __shared__ float gts_s[MM];
    __shared__ int fp_s[MM];
    __shared__ int tp_s[MM];
    int t = threadIdx.x;
    if (t < MM) {
        float s = 0.f;
        int any = 0;
        for (int g = 0; g < MM; g++) {
            unsigned c = d_ov[g * MM + t];
            s += (float)c;
            if (g >= 1) any |= (c > 0u);
        }
        prs[t] = s;
        tp_s[t] = any;
    }
    __syncthreads();
    if (t >= 1 && t < MM) {
        float inter = 0.f, uni = 0.f;
        float gts = (float)d_ov[t * MM + 0];
        for (int p = 1; p < MM; p++) {
            unsigned c = d_ov[t * MM + p];
            float cf = (float)c;
            inter += cf;
            gts += cf;
            if (c > 0u) uni += prs[p];
        }
        float d = 0.f;
        if (inter > 0.f) d = 2.f * inter / fmaxf(uni + gts, 1.f);
        dice_s[t] = d;
        gts_s[t] = gts;
        fp_s[t] = (prs[t] > 0.f && !tp_s[t]) ? 1 : 0;
    }
    __syncthreads();
    if (t == 0) {
        float ld = 0.f, ng = 0.f, nf = 0.f;
        for (int g = 1; g < MM; g++) {
            ld += dice_s[g];
            ng += (gts_s[g] > 0.f) ? 1.f : 0.f;
            nf += (float)fp_s[g];
        }
        out[0] = ld / (ng + nf);
    }
}

extern "C" void kernel_launch(void* const* d_in, const int* in_sizes, int n_in,
                              void* d_out, int out_size) {
    const float* x = (const float*)d_in[0];
    const float* y = (const float*)d_in[1];
    float* out = (float*)d_out;

    k_zero<<<(MM * MM + 255) / 256, 256>>>();
    k_init<<<(NVOL * VOX + 255) / 256, 256>>>(x, y);
    k_merge<<<512, 256>>>();
    k_flatten<<<512, 256>>>();
    k_maxroot<<<512, 256>>>();
    k_compact<<<1, 32>>>();
    k_overlap<<<512, 256>>>();
    k_final<<<1, 128>>>(out);
}

// round 2
// speedup vs baseline: 6.1354x; 6.1354x over previous
#include <cuda_runtime.h>
#include <climits>

// InstanceDiceLoss — single persistent kernel, 148 co-resident blocks,
// software grid barriers between phases.
//
// Phases: 0 zero counters/hist | 1 threshold->mask+UF-init+active list
//         2 ECL-CC union over 13 fwd neighbors | 3 flatten roots
//         4 per-root maxid + root list | 5 rank/compact (block 0)
//         6 overlap histogram | 7 dice scalar (block 0)

#define VOXB 21
#define VOX (1 << VOXB)            // 128^3
#define NVOL 4                     // gt_s0, gt_s1, pr_s0, pr_s1
#define TOTV (NVOL * VOX)
#define MAXLAB 64
#define MM 65
#define NBLK 148
#define NTHR 256
#define NT (NBLK * NTHR)
#define NC (TOTV / 4)              // float4 chunks
#define ITERS ((NC + NT - 1) / NT)

__device__ int      d_W[TOTV];             // union-find parent (active only)
__device__ int      d_A[TOTV];             // per-root: maxid then compact id
__device__ unsigned d_mask[TOTV / 32];     // foreground bitmask
__device__ int      d_active[TOTV];        // active voxel list (global ids)
__device__ int      d_activeCnt;
__device__ int      d_rootCnt[NVOL];
__device__ int      d_rootList[NVOL * MAXLAB];
__device__ unsigned d_ov[MM * MM];         // overlap histogram
__device__ unsigned d_barCnt = 0;
__device__ unsigned d_barGen = 0;

__device__ __forceinline__ void gsync() {
    __syncthreads();
    if (threadIdx.x == 0) {
        __threadfence();
        unsigned gen = atomicAdd(&d_barGen, 0u);
        if (atomicAdd(&d_barCnt, 1u) == NBLK - 1) {
            d_barCnt = 0;
            __threadfence();
            atomicExch(&d_barGen, gen + 1u);
        } else {
            while (atomicAdd(&d_barGen, 0u) == gen) __nanosleep(64);
            __threadfence();
        }
    }
    __syncthreads();
}

// ECL-CC representative: walk to root with path-halving via plain stores
// (race-benign: only non-root entries are overwritten, values only decrease).
__device__ __forceinline__ int rep(int* W, int v) {
    int curr = W[v];
    if (curr != v) {
        int prev = v, next;
        while (curr > (next = W[curr])) {
            W[prev] = next;
            prev = curr;
            curr = next;
        }
    }
    return curr;
}

// ECL-CC union: CAS only on roots.
__device__ __forceinline__ void join(int* W, int a, int b) {
    int vs = rep(W, a), os = rep(W, b);
    bool repeat;
    do {
        repeat = false;
        if (vs != os) {
            int ret;
            if (vs < os) {
                if ((ret = atomicCAS(&W[os], os, vs)) != os) { os = ret; repeat = true; }
            } else {
                if ((ret = atomicCAS(&W[vs], vs, os)) != vs) { vs = ret; repeat = true; }
            }
        }
    } while (repeat);
}

__global__ void __launch_bounds__(NTHR, 1)
k_all(const float* __restrict__ x, const float* __restrict__ y,
      float* __restrict__ out) {
    const int tid  = blockIdx.x * NTHR + threadIdx.x;
    const int lane = threadIdx.x & 31;

    // ---- Phase 0: zero counters + histogram ----
    if (tid == 0) d_activeCnt = 0;
    if (tid < NVOL) d_rootCnt[tid] = 0;
    for (int i = tid; i < MM * MM; i += NT) d_ov[i] = 0u;
    gsync();

    // ---- Phase 1: threshold -> mask bits + UF init + active list ----
    {
        const float4* y4 = (const float4*)y;
        const float4* x4 = (const float4*)x;
        for (int it = 0; it < ITERS; it++) {
            int c = tid + it * NT;           // chunk of 4 voxels
            unsigned nib = 0u;
            int g0 = c << 2;
            if (c < NC) {
                float4 v = (c < (VOX / 2)) ? y4[c] : x4[c - (VOX / 2)];
                nib = (v.x > 0.5f ? 1u : 0u) | (v.y > 0.5f ? 2u : 0u) |
                      (v.z > 0.5f ? 4u : 0u) | (v.w > 0.5f ? 8u : 0u);
            }
            // combine 8 nibbles -> one 32-bit mask word per 8-lane group
            unsigned w = nib << (4 * (lane & 7));
            w |= __shfl_xor_sync(0xffffffffu, w, 1);
            w |= __shfl_xor_sync(0xffffffffu, w, 2);
            w |= __shfl_xor_sync(0xffffffffu, w, 4);
            if ((lane & 7) == 0 && c < NC) d_mask[c >> 3] = w;

            // warp-aggregated active-list append + W init
            unsigned nact = __popc(nib);
            unsigned tot = __reduce_add_sync(0xffffffffu, nact);
            if (tot > 0u) {
                unsigned p = nact;
                #pragma unroll
                for (int d = 1; d < 32; d <<= 1) {
                    unsigned t = __shfl_up_sync(0xffffffffu, p, d);
                    if (lane >= d) p += t;
                }
                unsigned excl = p - nact;
                unsigned base;
                if (lane == 0) base = (unsigned)atomicAdd(&d_activeCnt, (int)tot);
                base = __shfl_sync(0xffffffffu, base, 0);
                int idx = (int)(base + excl);
                int local0 = g0 & (VOX - 1);
                #pragma unroll
                for (int j = 0; j < 4; j++) {
                    if ((nib >> j) & 1u) {
                        d_W[g0 + j] = local0 + j;
                        d_active[idx++] = g0 + j;
                    }
                }
            }
        }
    }
    gsync();

    const int n = d_activeCnt;

    // ---- Phase 2: union over 13 forward neighbors of 26-connectivity ----
    for (int t = tid; t < n; t += NT) {
        int gid = d_active[t];
        int vol = gid >> VOXB;
        int local = gid & (VOX - 1);
        int* W = d_W + (vol << VOXB);
        const unsigned* mk = d_mask + (vol << (VOXB - 5));
        int z = local >> 14, yy = (local >> 7) & 127, xx = local & 127;
        #pragma unroll
        for (int dz = 0; dz <= 1; dz++)
            #pragma unroll
            for (int dy = -1; dy <= 1; dy++)
                #pragma unroll
                for (int dx = -1; dx <= 1; dx++) {
                    if (dz == 0 && (dy < 0 || (dy == 0 && dx <= 0))) continue;
                    int nz = z + dz, ny = yy + dy, nx = xx + dx;
                    if ((unsigned)nz >= 128u || (unsigned)ny >= 128u ||
                        (unsigned)nx >= 128u)
                        continue;
                    int nl = (nz << 14) | (ny << 7) | nx;
                    if ((mk[nl >> 5] >> (nl & 31)) & 1u) join(W, local, nl);
                }
    }
    gsync();

    // ---- Phase 3: flatten to final roots, init maxid slot at roots ----
    for (int t = tid; t < n; t += NT) {
        int gid = d_active[t];
        int vol = gid >> VOXB;
        int local = gid & (VOX - 1);
        const int* W = d_W + (vol << VOXB);
        int r = local, p = W[r];
        while (p != r) { r = p; p = W[r]; }
        d_W[gid] = r;
        if (r == local) d_A[gid] = 0;
    }
    gsync();

    // ---- Phase 4: per-component max initial id + root list ----
    for (int t = tid; t < n; t += NT) {
        int gid = d_active[t];
        int vol = gid >> VOXB;
        int local = gid & (VOX - 1);
        int r = d_W[gid];
        atomicMax(&d_A[(vol << VOXB) + r], local + 1);
        if (r == local) {
            int slot = atomicAdd(&d_rootCnt[vol], 1);
            if (slot < MAXLAB) d_rootList[vol * MAXLAB + slot] = local;
        }
    }
    gsync();

    // ---- Phase 5: compact ids by rank of component maxid (block 0) ----
    {
        __shared__ int s_mx[NVOL][MAXLAB];
        if (blockIdx.x == 0) {
            int t = threadIdx.x;          // 256 threads = 4 vols x 64 slots
            int vol = t >> 6, i = t & 63;
            int k = d_rootCnt[vol];
            if (k > MAXLAB) k = MAXLAB;
            int root = -1, m = INT_MAX;
            if (i < k) {
                root = d_rootList[vol * MAXLAB + i];
                m = d_A[(vol << VOXB) + root];
            }
            s_mx[vol][i] = m;
            __syncthreads();
            if (i < k) {
                int rank = 0;
                #pragma unroll 8
                for (int j = 0; j < MAXLAB; j++)
                    rank += (s_mx[vol][j] < m) ? 1 : 0;   // maxids unique
                d_A[(vol << VOXB) + root] = rank + 1;
            }
        }
    }
    gsync();

    // ---- Phase 6: 65x65 overlap histogram (batch-merged compact ids) ----
    for (int t = tid; t < n; t += NT) {
        int gid = d_active[t];
        int vol = gid >> VOXB;
        int local = gid & (VOX - 1);
        if (vol < 2) {                       // gt voxel: record (g, p)
            int g = d_A[(vol << VOXB) + d_W[gid]];
            int pg = ((vol + 2) << VOXB) + local;
            int p = ((d_mask[pg >> 5] >> (pg & 31)) & 1u)
                        ? d_A[((vol + 2) << VOXB) + d_W[pg]] : 0;
            atomicAdd(&d_ov[g * MM + p], 1u);
        } else {                             // pr voxel where gt is bg: (0, p)
            int gg = ((vol - 2) << VOXB) + local;
            if (!((d_mask[gg >> 5] >> (gg & 31)) & 1u)) {
                int p = d_A[(vol << VOXB) + d_W[gid]];
                atomicAdd(&d_ov[p], 1u);
            }
        }
    }
    gsync();

    // ---- Phase 7: dice scalar (block 0) ----
    if (blockIdx.x == 0) {
        __shared__ float prs[MM], dice_s[MM], gts_s[MM];
        __shared__ int fp_s[MM], tp_s[MM];
        int t = threadIdx.x;
        if (t < MM) {
            float s = 0.f; int any = 0;
            for (int g = 0; g < MM; g++) {
                unsigned c = d_ov[g * MM + t];
                s += (float)c;
                if (g >= 1) any |= (c > 0u);
            }
            prs[t] = s; tp_s[t] = any;
        }
        __syncthreads();
        if (t >= 1 && t < MM) {
            float inter = 0.f, uni = 0.f;
            float gts = (float)d_ov[t * MM + 0];
            for (int p = 1; p < MM; p++) {
                unsigned c = d_ov[t * MM + p];
                float cf = (float)c;
                inter += cf; gts += cf;
                if (c > 0u) uni += prs[p];
            }
            float d = (inter > 0.f) ? 2.f * inter / fmaxf(uni + gts, 1.f) : 0.f;
            dice_s[t] = d; gts_s[t] = gts;
            fp_s[t] = (prs[t] > 0.f && !tp_s[t]) ? 1 : 0;
        }
        __syncthreads();
        if (t == 0) {
            float ld = 0.f, ng = 0.f, nf = 0.f;
            for (int g = 1; g < MM; g++) {
                ld += dice_s[g];
                ng += (gts_s[g] > 0.f) ? 1.f : 0.f;
                nf += (float)fp_s[g];
            }
            out[0] = ld / (ng + nf);
        }
    }
}

extern "C" void kernel_launch(void* const* d_in, const int* in_sizes, int n_in,
                              void* d_out, int out_size) {
    const float* x = (const float*)d_in[0];
    const float* y = (const float*)d_in[1];
    k_all<<<NBLK, NTHR>>>(x, y, (float*)d_out);
}

// round 4
// speedup vs baseline: 8.1711x; 1.3318x over previous
#include <cuda_runtime.h>
#include <climits>

// InstanceDiceLoss — single persistent kernel, 148 blocks x 512 threads,
// software grid barriers. Self-cleaning counters (reset in tail) so each
// graph replay starts from a clean state.

#define VOXB 21
#define VOX (1 << VOXB)            // 128^3
#define NVOL 4                     // gt_s0, gt_s1, pr_s0, pr_s1
#define TOTV (NVOL * VOX)
#define NWORD (TOTV / 32)          // mask words (one per 32 voxels)
#define MAXLAB 64
#define MM 65
#define NBLK 148
#define NTHR 512
#define NT (NBLK * NTHR)
#define ITERS ((NWORD + NT - 1) / NT)

__device__ int      d_W[TOTV];             // union-find parent (active only)
__device__ int      d_A[TOTV];             // per-root: maxid then compact id
__device__ unsigned d_mask[NWORD];         // foreground bitmask
__device__ int      d_active[TOTV];        // active voxel list (global ids)
__device__ int      d_activeCnt = 0;
__device__ int      d_rootCnt[NVOL] = {0, 0, 0, 0};
__device__ int      d_rootList[NVOL * MAXLAB];
__device__ unsigned d_ov[MM * MM];         // zero-init (static) + tail reset
__device__ unsigned d_barCnt = 0;
__device__ unsigned d_barGen = 0;

__device__ __forceinline__ void gsync() {
    __syncthreads();
    if (threadIdx.x == 0) {
        __threadfence();
        unsigned gen = atomicAdd(&d_barGen, 0u);
        if (atomicAdd(&d_barCnt, 1u) == NBLK - 1) {
            d_barCnt = 0;
            __threadfence();
            atomicExch(&d_barGen, gen + 1u);
        } else {
            while (atomicAdd(&d_barGen, 0u) == gen) __nanosleep(32);
            __threadfence();
        }
    }
    __syncthreads();
}

// ECL-CC representative walk with path compression via plain stores.
__device__ __forceinline__ int rep(int* W, int v) {
    int curr = W[v];
    if (curr != v) {
        int prev = v, next;
        while (curr > (next = W[curr])) {
            W[prev] = next;
            prev = curr;
            curr = next;
        }
    }
    return curr;
}

// ECL-CC union: CAS only on roots.
__device__ __forceinline__ void join(int* W, int a, int b) {
    int vs = rep(W, a), os = rep(W, b);
    bool repeat;
    do {
        repeat = false;
        if (vs != os) {
            int ret;
            if (vs < os) {
                if ((ret = atomicCAS(&W[os], os, vs)) != os) { os = ret; repeat = true; }
            } else {
                if ((ret = atomicCAS(&W[vs], vs, os)) != vs) { vs = ret; repeat = true; }
            }
        }
    } while (repeat);
}

__global__ void __launch_bounds__(NTHR, 1)
k_all(const float* __restrict__ x, const float* __restrict__ y,
      float* __restrict__ out) {
    const int tid  = blockIdx.x * NTHR + threadIdx.x;
    const int lane = threadIdx.x & 31;

    __shared__ unsigned s_ov[MM * MM];

    // ---- Phase 1: threshold -> one mask word/thread (MLP=8), UF init, list ----
    #pragma unroll
    for (int it = 0; it < ITERS; it++) {
        int w = tid + it * NT;
        bool valid = w < NWORD;
        unsigned word = 0u;
        int g0 = w << 5;                       // first global voxel of word
        if (valid) {
            const float4* src = (g0 < 2 * VOX) ? (const float4*)(y + g0)
                                               : (const float4*)(x + (g0 - 2 * VOX));
            #pragma unroll
            for (int j = 0; j < 8; j++) {      // 8 independent 16B loads
                float4 v = src[j];
                unsigned nib = (v.x > 0.5f ? 1u : 0u) | (v.y > 0.5f ? 2u : 0u) |
                               (v.z > 0.5f ? 4u : 0u) | (v.w > 0.5f ? 8u : 0u);
                word |= nib << (4 * j);
            }
            d_mask[w] = word;
        }
        int cnt = __popc(word);
        unsigned tot = __reduce_add_sync(0xffffffffu, (unsigned)cnt);
        if (tot > 0u) {
            unsigned p = (unsigned)cnt;        // inclusive warp scan
            #pragma unroll
            for (int d = 1; d < 32; d <<= 1) {
                unsigned t = __shfl_up_sync(0xffffffffu, p, d);
                if (lane >= d) p += t;
            }
            unsigned base;
            if (lane == 31) base = (unsigned)atomicAdd(&d_activeCnt, (int)p);
            base = __shfl_sync(0xffffffffu, base, 31);
            int idx = (int)base + (int)p - cnt;   // base + exclusive scan
            int local0 = g0 & (VOX - 1);
            unsigned ww = word;
            while (ww) {
                int b = __ffs(ww) - 1;
                ww &= ww - 1u;
                int gid = g0 + b;
                d_W[gid] = local0 + b;
                d_A[gid] = 0;
                d_active[idx++] = gid;
            }
        }
    }
    gsync();

    const int n = d_activeCnt;

    // ---- Phase 2: union over 13 forward neighbors of 26-connectivity ----
    for (int t = tid; t < n; t += NT) {
        int gid = d_active[t];
        int vol = gid >> VOXB;
        int local = gid & (VOX - 1);
        int* W = d_W + (vol << VOXB);
        const unsigned* mk = d_mask + (vol << (VOXB - 5));
        int z = local >> 14, yy = (local >> 7) & 127, xx = local & 127;
        #pragma unroll
        for (int dz = 0; dz <= 1; dz++)
            #pragma unroll
            for (int dy = -1; dy <= 1; dy++)
                #pragma unroll
                for (int dx = -1; dx <= 1; dx++) {
                    if (dz == 0 && (dy < 0 || (dy == 0 && dx <= 0))) continue;
                    int nz = z + dz, ny = yy + dy, nx = xx + dx;
                    if ((unsigned)nz >= 128u || (unsigned)ny >= 128u ||
                        (unsigned)nx >= 128u)
                        continue;
                    int nl = (nz << 14) | (ny << 7) | nx;
                    if ((mk[nl >> 5] >> (nl & 31)) & 1u) join(W, local, nl);
                }
    }
    gsync();

    // ---- Phase 3+4: flatten to final root, per-root maxid, root list ----
    for (int t = tid; t < n; t += NT) {
        int gid = d_active[t];
        int vol = gid >> VOXB;
        int local = gid & (VOX - 1);
        int* W = d_W + (vol << VOXB);
        int r = local, p = W[r];
        while (p != r) { r = p; p = W[r]; }
        d_W[gid] = r;
        atomicMax(&d_A[(vol << VOXB) + r], local + 1);
        if (r == local) {
            int slot = atomicAdd(&d_rootCnt[vol], 1);
            if (slot < MAXLAB) d_rootList[vol * MAXLAB + slot] = local;
        }
    }
    gsync();

    // ---- Phase 5: compact ids = rank of component maxid (block 0) ----
    // NON-DIVERGENT: all NTHR threads of block 0 reach __syncthreads();
    // only the first NVOL*MAXLAB do the work.
    if (blockIdx.x == 0) {
        __shared__ int s_mx[NVOL][MAXLAB];
        int t = threadIdx.x;
        int vol = (t >> 6) & (NVOL - 1), i = t & 63;
        int k = 0, root = -1, m = INT_MAX;
        if (t < NVOL * MAXLAB) {
            k = d_rootCnt[vol];
            if (k > MAXLAB) k = MAXLAB;
            if (i < k) {
                root = d_rootList[vol * MAXLAB + i];
                m = d_A[(vol << VOXB) + root];
            }
            s_mx[vol][i] = m;
        }
        __syncthreads();
        if (t < NVOL * MAXLAB && i < k) {
            int rank = 0;
            #pragma unroll 8
            for (int j = 0; j < MAXLAB; j++)
                rank += (s_mx[vol][j] < m) ? 1 : 0;   // maxids unique
            d_A[(vol << VOXB) + root] = rank + 1;
        }
    }
    gsync();

    // ---- Phase 6: overlap histogram (smem-aggregated per block) ----
    for (int i = threadIdx.x; i < MM * MM; i += NTHR) s_ov[i] = 0u;
    __syncthreads();
    for (int t = tid; t < n; t += NT) {
        int gid = d_active[t];
        int vol = gid >> VOXB;
        int local = gid & (VOX - 1);
        if (vol < 2) {                       // gt voxel: record (g, p)
            int g = d_A[(vol << VOXB) + d_W[gid]];
            int pg = ((vol + 2) << VOXB) + local;
            int p = ((d_mask[pg >> 5] >> (pg & 31)) & 1u)
                        ? d_A[((vol + 2) << VOXB) + d_W[pg]] : 0;
            atomicAdd(&s_ov[g * MM + p], 1u);
        } else {                             // pr voxel where gt is bg: (0, p)
            int gg = ((vol - 2) << VOXB) + local;
            if (!((d_mask[gg >> 5] >> (gg & 31)) & 1u)) {
                int p = d_A[(vol << VOXB) + d_W[gid]];
                atomicAdd(&s_ov[p], 1u);
            }
        }
    }
    __syncthreads();
    for (int i = threadIdx.x; i < MM * MM; i += NTHR) {
        unsigned c = s_ov[i];
        if (c) atomicAdd(&d_ov[i], c);
    }
    gsync();

    // ---- Phase 7: dice scalar + self-clean (block 0) ----
    if (blockIdx.x == 0) {
        __shared__ float prs[MM], dice_s[MM], gts_s[MM];
        __shared__ int fp_s[MM], tp_s[MM];
        int t = threadIdx.x;
        if (t < MM) {
            float s = 0.f; int any = 0;
            for (int g = 0; g < MM; g++) {
                unsigned c = d_ov[g * MM + t];
                s += (float)c;
                if (g >= 1) any |= (c > 0u);
            }
            prs[t] = s; tp_s[t] = any;
        }
        __syncthreads();
        if (t >= 1 && t < MM) {
            float inter = 0.f, uni = 0.f;
            float gts = (float)d_ov[t * MM + 0];
            for (int p = 1; p < MM; p++) {
                unsigned c = d_ov[t * MM + p];
                float cf = (float)c;
                inter += cf; gts += cf;
                if (c > 0u) uni += prs[p];
            }
            float d = (inter > 0.f) ? 2.f * inter / fmaxf(uni + gts, 1.f) : 0.f;
            dice_s[t] = d; gts_s[t] = gts;
            fp_s[t] = (prs[t] > 0.f && !tp_s[t]) ? 1 : 0;
        }
        __syncthreads();
        if (t == 0) {
            float ld = 0.f, ng = 0.f, nf = 0.f;
            for (int g = 1; g < MM; g++) {
                ld += dice_s[g];
                ng += (gts_s[g] > 0.f) ? 1.f : 0.f;
                nf += (float)fp_s[g];
            }
            out[0] = ld / (ng + nf);
        }
        __syncthreads();
        // self-clean for next replay (stream order makes this visible)
        for (int i = threadIdx.x; i < MM * MM; i += NTHR) d_ov[i] = 0u;
        if (t == 0) d_activeCnt = 0;
        if (t < NVOL) d_rootCnt[t] = 0;
    }
}

extern "C" void kernel_launch(void* const* d_in, const int* in_sizes, int n_in,
                              void* d_out, int out_size) {
    const float* x = (const float*)d_in[0];
    const float* y = (const float*)d_in[1];
    k_all<<<NBLK, NTHR>>>(x, y, (float*)d_out);
}